// round 9
// baseline (speedup 1.0000x reference)
#include <cuda_runtime.h>
#include <cstdint>

// Spatial masked-pool-gate, single streaming pass.
//   xp = pad(x, 110->112); pooled = 4x4 sumpool(xp * mask);
//   out = (pooled > 0) ? xp : 0, cropped to 110x110.
//
// R9 variant: TWO vertically-stacked 4x4 patches per thread (8 rows x 4 cols,
// two independent gates). Doubles front-batched load MLP per thread and halves
// per-patch index arithmetic vs the 1-patch/thread converged kernel.
// float2 x/out + float4 mask, default cache policy (measured best combo).

namespace {
constexpr int HIN  = 110;
constexpr int HPAD = 112;
constexpr int PP   = 28;               // patch columns (112/4)
constexpr int PR2  = 14;               // patch-row PAIRS per side (28/2)
constexpr int NCH  = 64 * 64;
constexpr int CH_X = HIN * HIN;        // 12100
constexpr int CH_M = HPAD * HPAD;      // 12544
}

__global__ __launch_bounds__(256)
void spatial_gate_kernel(const float* __restrict__ x,
                         const float* __restrict__ mask,
                         float* __restrict__ out)
{
    const int p   = blockIdx.x * 256 + threadIdx.x;   // exact grid, no guard
    const int pc  = p % PP;
    const int t   = p / PP;
    const int pr2 = t % PR2;
    const int ch  = t / PR2;

    const float* __restrict__ xc = x    + (size_t)ch * CH_X;
    const float* __restrict__ mc = mask + (size_t)ch * CH_M;
    float*       __restrict__ oc = out  + (size_t)ch * CH_X;

    const int c0 = pc * 4;
    const int r0 = pr2 * 8;                // two stacked patches: rows r0..r0+7
    const bool full_c = (c0 + 4 <= HIN);   // false only for pc == 27

    float xv[8][4];
    float sum0 = 0.0f;   // patch rows r0..r0+3
    float sum1 = 0.0f;   // patch rows r0+4..r0+7

    #pragma unroll
    for (int i = 0; i < 8; ++i) {
        const int row = r0 + i;
        if (row < HIN) {
            const float* xr = xc + row * HIN + c0;
            const float4 mv = *reinterpret_cast<const float4*>(mc + row * HPAD + c0);
            const float2 a  = *reinterpret_cast<const float2*>(xr);
            float s = a.x * mv.x + a.y * mv.y;
            xv[i][0] = a.x; xv[i][1] = a.y;
            if (full_c) {
                const float2 b = *reinterpret_cast<const float2*>(xr + 2);
                xv[i][2] = b.x; xv[i][3] = b.y;
                s += b.x * mv.z + b.y * mv.w;
            }
            if (i < 4) sum0 += s; else sum1 += s;
        }
    }

    const float f0 = (sum0 > 0.0f) ? 1.0f : 0.0f;
    const float f1 = (sum1 > 0.0f) ? 1.0f : 0.0f;

    #pragma unroll
    for (int i = 0; i < 8; ++i) {
        const int row = r0 + i;
        if (row < HIN) {
            const float f = (i < 4) ? f0 : f1;
            float* orow = oc + row * HIN + c0;
            float2 a;
            a.x = xv[i][0] * f;
            a.y = xv[i][1] * f;
            *reinterpret_cast<float2*>(orow) = a;
            if (full_c) {
                float2 b;
                b.x = xv[i][2] * f;
                b.y = xv[i][3] * f;
                *reinterpret_cast<float2*>(orow + 2) = b;
            }
        }
    }
}

extern "C" void kernel_launch(void* const* d_in, const int* in_sizes, int n_in,
                              void* d_out, int out_size)
{
    const float* x    = (const float*)d_in[0];
    const float* mask = (const float*)d_in[1];
    // d_in[2] is p_size (== 4), compile-time constant here.
    float* out = (float*)d_out;

    const int total_threads = NCH * PR2 * PP;   // 1,605,632
    const int blocks = total_threads / 256;     // 6,272 exact
    spatial_gate_kernel<<<blocks, 256>>>(x, mask, out);
}

// round 10
// speedup vs baseline: 1.0186x; 1.0186x over previous
#include <cuda_runtime.h>
#include <cstdint>

// Spatial masked-pool-gate, single streaming pass (R1 winner config,
// 512-thread-block probe):
//   xp = pad(x, 110->112); pooled = 4x4 sumpool(xp * mask);
//   out = (pooled > 0) ? xp : 0, cropped to 110x110.
//
// One thread per 4x4 patch; x read once and register-held across pool->gate
// (traffic floor). Homogeneous float2 x/out + float4 mask, default cache
// policy. Measured sweep: wider loads, streaming hints, and 2-patch/thread
// all regressed; DRAM queue is the sole binding resource at ~79-80% of spec.

namespace {
constexpr int HIN  = 110;
constexpr int HPAD = 112;
constexpr int PP   = 28;               // patches per side (112/4)
constexpr int NCH  = 64 * 64;          // N*C channels
constexpr int CH_X = HIN * HIN;        // 12100 floats per channel (x/out)
constexpr int CH_M = HPAD * HPAD;      // 12544 floats per channel (mask)
constexpr int TPB  = 512;
}

__global__ __launch_bounds__(TPB)
void spatial_gate_kernel(const float* __restrict__ x,
                         const float* __restrict__ mask,
                         float* __restrict__ out)
{
    const int p  = blockIdx.x * TPB + threadIdx.x;   // exact grid, no guard
    const int pc = p % PP;
    const int t  = p / PP;
    const int pr = t % PP;
    const int ch = t / PP;

    const float* __restrict__ xc = x    + (size_t)ch * CH_X;
    const float* __restrict__ mc = mask + (size_t)ch * CH_M;
    float*       __restrict__ oc = out  + (size_t)ch * CH_X;

    const int c0 = pc * 4;
    const int r0 = pr * 4;
    const bool full_c = (c0 + 4 <= HIN);   // false only for pc == 27 (cols 108..111)

    float xv[4][4];
    float sum = 0.0f;

    #pragma unroll
    for (int i = 0; i < 4; ++i) {
        const int row = r0 + i;
        if (row < HIN) {
            const float*  xr = xc + row * HIN + c0;
            const float4  mv = *reinterpret_cast<const float4*>(mc + row * HPAD + c0);
            const float2  a  = *reinterpret_cast<const float2*>(xr);
            xv[i][0] = a.x; xv[i][1] = a.y;
            sum += a.x * mv.x;
            sum += a.y * mv.y;
            if (full_c) {
                const float2 b = *reinterpret_cast<const float2*>(xr + 2);
                xv[i][2] = b.x; xv[i][3] = b.y;
                sum += b.x * mv.z;
                sum += b.y * mv.w;
            }
        }
    }

    const float f = (sum > 0.0f) ? 1.0f : 0.0f;

    #pragma unroll
    for (int i = 0; i < 4; ++i) {
        const int row = r0 + i;
        if (row < HIN) {
            float* orow = oc + row * HIN + c0;
            float2 a;
            a.x = xv[i][0] * f;
            a.y = xv[i][1] * f;
            *reinterpret_cast<float2*>(orow) = a;
            if (full_c) {
                float2 b;
                b.x = xv[i][2] * f;
                b.y = xv[i][3] * f;
                *reinterpret_cast<float2*>(orow + 2) = b;
            }
        }
    }
}

extern "C" void kernel_launch(void* const* d_in, const int* in_sizes, int n_in,
                              void* d_out, int out_size)
{
    const float* x    = (const float*)d_in[0];
    const float* mask = (const float*)d_in[1];
    // d_in[2] is p_size (== 4), compile-time constant here.
    float* out = (float*)d_out;

    const int total_patches = NCH * PP * PP;       // 3,211,264
    const int blocks = total_patches / TPB;        // 6,272 exact
    spatial_gate_kernel<<<blocks, TPB>>>(x, mask, out);
}

// round 11
// speedup vs baseline: 1.0296x; 1.0108x over previous
#include <cuda_runtime.h>
#include <cstdint>

// Spatial masked-pool-gate, single streaming pass — FINAL (R1 config).
//   xp = pad(x, 110->112); pooled = 4x4 sumpool(xp * mask);
//   out = (pooled > 0) ? xp : 0, cropped to 110x110.
//
// One thread per 4x4 patch; x read exactly once and register-held across
// pool->gate (traffic floor ~598 MB). Homogeneous float2 x/out accesses +
// float4 mask, default cache policy, 256 threads/block.
//
// Measured sweep (kernel us @ DRAM%): this config 87.7/89.0 @ ~79-80%;
// float4-even rows 89.4 @ 79.6; streaming hints 90.7 @ 77.7;
// 2 patches/thread 91.8 @ 77.3; 512 TPB 89.2 @ 79.1. All alternatives
// neutral-to-worse: the kernel sits at the mixed-R/W HBM ceiling.

namespace {
constexpr int HIN  = 110;
constexpr int HPAD = 112;
constexpr int PP   = 28;               // patches per side (112/4)
constexpr int NCH  = 64 * 64;          // N*C channels
constexpr int CH_X = HIN * HIN;        // 12100 floats per channel (x/out)
constexpr int CH_M = HPAD * HPAD;      // 12544 floats per channel (mask)
}

__global__ __launch_bounds__(256)
void spatial_gate_kernel(const float* __restrict__ x,
                         const float* __restrict__ mask,
                         float* __restrict__ out)
{
    const int p  = blockIdx.x * 256 + threadIdx.x;   // exact grid, no guard
    const int pc = p % PP;
    const int t  = p / PP;
    const int pr = t % PP;
    const int ch = t / PP;

    const float* __restrict__ xc = x    + (size_t)ch * CH_X;
    const float* __restrict__ mc = mask + (size_t)ch * CH_M;
    float*       __restrict__ oc = out  + (size_t)ch * CH_X;

    const int c0 = pc * 4;
    const int r0 = pr * 4;
    const bool full_c = (c0 + 4 <= HIN);   // false only for pc == 27 (cols 108..111)

    float xv[4][4];
    float sum = 0.0f;

    #pragma unroll
    for (int i = 0; i < 4; ++i) {
        const int row = r0 + i;
        if (row < HIN) {
            const float*  xr = xc + row * HIN + c0;
            const float4  mv = *reinterpret_cast<const float4*>(mc + row * HPAD + c0);
            const float2  a  = *reinterpret_cast<const float2*>(xr);
            xv[i][0] = a.x; xv[i][1] = a.y;
            sum += a.x * mv.x;
            sum += a.y * mv.y;
            if (full_c) {
                const float2 b = *reinterpret_cast<const float2*>(xr + 2);
                xv[i][2] = b.x; xv[i][3] = b.y;
                sum += b.x * mv.z;
                sum += b.y * mv.w;
            }
        }
    }

    const float f = (sum > 0.0f) ? 1.0f : 0.0f;

    #pragma unroll
    for (int i = 0; i < 4; ++i) {
        const int row = r0 + i;
        if (row < HIN) {
            float* orow = oc + row * HIN + c0;
            float2 a;
            a.x = xv[i][0] * f;
            a.y = xv[i][1] * f;
            *reinterpret_cast<float2*>(orow) = a;
            if (full_c) {
                float2 b;
                b.x = xv[i][2] * f;
                b.y = xv[i][3] * f;
                *reinterpret_cast<float2*>(orow + 2) = b;
            }
        }
    }
}

extern "C" void kernel_launch(void* const* d_in, const int* in_sizes, int n_in,
                              void* d_out, int out_size)
{
    const float* x    = (const float*)d_in[0];
    const float* mask = (const float*)d_in[1];
    // d_in[2] is p_size (== 4), compile-time constant here.
    float* out = (float*)d_out;

    const int total_patches = NCH * PP * PP;       // 3,211,264
    const int blocks = total_patches / 256;        // 12,544 exact
    spatial_gate_kernel<<<blocks, 256>>>(x, mask, out);
}

// round 12
// speedup vs baseline: 1.0508x; 1.0206x over previous
#include <cuda_runtime.h>
#include <cstdint>

// Spatial masked-pool-gate, single streaming pass — FINAL (R1 config).
//   xp = pad(x, 110->112); pooled = 4x4 sumpool(xp * mask);
//   out = (pooled > 0) ? xp : 0, cropped to 110x110.
//
// One thread per 4x4 patch; x read exactly once and register-held across
// pool->gate (traffic at the mandatory floor; measured DRAM bytes ~555 MB).
// Homogeneous float2 x/out accesses + float4 mask, default cache policy,
// 256 threads/block.
//
// Converged: 3 runs of this source give 87.7/89.0/88.1 us kernel @ 79-80%
// DRAM-of-spec (the mixed-R/W HBM ceiling). All explored alternatives
// (float4-even rows, streaming hints, 2 patches/thread, 512 TPB) measured
// neutral-to-worse. No unexplored lever with positive predicted delta.

namespace {
constexpr int HIN  = 110;
constexpr int HPAD = 112;
constexpr int PP   = 28;               // patches per side (112/4)
constexpr int NCH  = 64 * 64;          // N*C channels
constexpr int CH_X = HIN * HIN;        // 12100 floats per channel (x/out)
constexpr int CH_M = HPAD * HPAD;      // 12544 floats per channel (mask)
}

__global__ __launch_bounds__(256)
void spatial_gate_kernel(const float* __restrict__ x,
                         const float* __restrict__ mask,
                         float* __restrict__ out)
{
    const int p  = blockIdx.x * 256 + threadIdx.x;   // exact grid, no guard
    const int pc = p % PP;
    const int t  = p / PP;
    const int pr = t % PP;
    const int ch = t / PP;

    const float* __restrict__ xc = x    + (size_t)ch * CH_X;
    const float* __restrict__ mc = mask + (size_t)ch * CH_M;
    float*       __restrict__ oc = out  + (size_t)ch * CH_X;

    const int c0 = pc * 4;
    const int r0 = pr * 4;
    const bool full_c = (c0 + 4 <= HIN);   // false only for pc == 27 (cols 108..111)

    float xv[4][4];
    float sum = 0.0f;

    #pragma unroll
    for (int i = 0; i < 4; ++i) {
        const int row = r0 + i;
        if (row < HIN) {
            const float*  xr = xc + row * HIN + c0;
            const float4  mv = *reinterpret_cast<const float4*>(mc + row * HPAD + c0);
            const float2  a  = *reinterpret_cast<const float2*>(xr);
            xv[i][0] = a.x; xv[i][1] = a.y;
            sum += a.x * mv.x;
            sum += a.y * mv.y;
            if (full_c) {
                const float2 b = *reinterpret_cast<const float2*>(xr + 2);
                xv[i][2] = b.x; xv[i][3] = b.y;
                sum += b.x * mv.z;
                sum += b.y * mv.w;
            }
        }
    }

    const float f = (sum > 0.0f) ? 1.0f : 0.0f;

    #pragma unroll
    for (int i = 0; i < 4; ++i) {
        const int row = r0 + i;
        if (row < HIN) {
            float* orow = oc + row * HIN + c0;
            float2 a;
            a.x = xv[i][0] * f;
            a.y = xv[i][1] * f;
            *reinterpret_cast<float2*>(orow) = a;
            if (full_c) {
                float2 b;
                b.x = xv[i][2] * f;
                b.y = xv[i][3] * f;
                *reinterpret_cast<float2*>(orow + 2) = b;
            }
        }
    }
}

extern "C" void kernel_launch(void* const* d_in, const int* in_sizes, int n_in,
                              void* d_out, int out_size)
{
    const float* x    = (const float*)d_in[0];
    const float* mask = (const float*)d_in[1];
    // d_in[2] is p_size (== 4), compile-time constant here.
    float* out = (float*)d_out;

    const int total_patches = NCH * PP * PP;       // 3,211,264
    const int blocks = total_patches / 256;        // 12,544 exact
    spatial_gate_kernel<<<blocks, 256>>>(x, mask, out);
}